// round 1
// baseline (speedup 1.0000x reference)
#include <cuda_runtime.h>
#include <math.h>

#define TT 1024
#define BB 32
#define DD 1024
#define BD (BB*DD)          // 32768
#define TBD (TT*BD)         // 33554432

// ---------------- scratch (static device allocations are allowed) ----------
__device__ float g_xRx[TBD];        // x @ R_x^T + b
__device__ float g_xWd[TBD];        // x @ W_delta^T + b_delta
__device__ float g_pv[4*BD];        // split-K partials for v     [ks][b][e]
__device__ float g_pd[4*BD];        // split-K partials for delta [ks][b][e]

__device__ unsigned g_b1cnt[32*32];            // per-etile-group counters (stride 32)
__device__ volatile unsigned g_b1gen[32*32];   // per-group generation
__device__ unsigned g_b2cnt;                   // global barrier counter
__device__ volatile unsigned g_b2gen;          // global generation

// ---------------- init: copy h0 -> h[0], reset barrier state ---------------
__global__ void init_kernel(const float* __restrict__ h0, float* __restrict__ hout) {
    int i = blockIdx.x * blockDim.x + threadIdx.x;
    if (i < BD) hout[i] = h0[i];
    if (i < 32) { g_b1cnt[i*32] = 0u; g_b1gen[i*32] = 0u; }
    if (i == 0) { g_b2cnt = 0u; g_b2gen = 0u; }
}

// ---------------- precompute GEMM:  C[32768 x 2048] = X @ [R_x; W_delta]^T -
// block tile 128(m) x 64(n), BK=16, 256 threads, 8x4 micro-tile
__global__ void __launch_bounds__(256) pre_gemm(
    const float* __restrict__ X,
    const float* __restrict__ Rx,
    const float* __restrict__ Wd,
    const float* __restrict__ bb,
    const float* __restrict__ bd)
{
    __shared__ float As[16*132];   // [k][m] padded
    __shared__ float Bs[16*68];    // [k][n] padded

    const int tid = threadIdx.x;
    const int nt  = blockIdx.x & 31;   // 32 n-tiles of 64 (cols 0..2047)
    const int mt  = blockIdx.x >> 5;   // 256 m-tiles of 128
    const int m0  = mt << 7;
    const int n0  = nt << 6;
    const int isRx = (n0 < DD);
    const float* Wbase = isRx ? (Rx + (size_t)n0 * DD) : (Wd + (size_t)(n0 - DD) * DD);

    const int ar0 = tid >> 2;      // 0..63
    const int akq = tid & 3;       // k-quad 0..3
    const float* aptr0 = X + (size_t)(m0 + ar0)      * DD + akq*4;
    const float* aptr1 = X + (size_t)(m0 + ar0 + 64) * DD + akq*4;
    const float* bptr  = Wbase + (size_t)ar0 * DD + akq*4;

    const int tm = tid >> 4;       // 0..15 -> m base tm*8
    const int tn = tid & 15;       // n base tn*4

    float acc[8][4];
    #pragma unroll
    for (int i = 0; i < 8; ++i)
        #pragma unroll
        for (int j = 0; j < 4; ++j) acc[i][j] = 0.f;

    float4 a0 = *(const float4*)(aptr0);
    float4 a1 = *(const float4*)(aptr1);
    float4 bq = *(const float4*)(bptr);

    for (int kt = 0; kt < 64; ++kt) {
        // stage current regs into smem (transposed)
        {
            const int kk = akq * 4;
            As[(kk+0)*132 + ar0]      = a0.x;
            As[(kk+1)*132 + ar0]      = a0.y;
            As[(kk+2)*132 + ar0]      = a0.z;
            As[(kk+3)*132 + ar0]      = a0.w;
            As[(kk+0)*132 + ar0 + 64] = a1.x;
            As[(kk+1)*132 + ar0 + 64] = a1.y;
            As[(kk+2)*132 + ar0 + 64] = a1.z;
            As[(kk+3)*132 + ar0 + 64] = a1.w;
            Bs[(kk+0)*68 + ar0] = bq.x;
            Bs[(kk+1)*68 + ar0] = bq.y;
            Bs[(kk+2)*68 + ar0] = bq.z;
            Bs[(kk+3)*68 + ar0] = bq.w;
        }
        __syncthreads();
        if (kt < 63) {   // prefetch next tile into regs while computing
            a0 = *(const float4*)(aptr0 + (kt+1)*16);
            a1 = *(const float4*)(aptr1 + (kt+1)*16);
            bq = *(const float4*)(bptr  + (kt+1)*16);
        }
        #pragma unroll
        for (int k = 0; k < 16; ++k) {
            float4 x0 = *(const float4*)(As + k*132 + tm*8);
            float4 x1 = *(const float4*)(As + k*132 + tm*8 + 4);
            float4 w  = *(const float4*)(Bs + k*68  + tn*4);
            acc[0][0]=fmaf(x0.x,w.x,acc[0][0]); acc[0][1]=fmaf(x0.x,w.y,acc[0][1]); acc[0][2]=fmaf(x0.x,w.z,acc[0][2]); acc[0][3]=fmaf(x0.x,w.w,acc[0][3]);
            acc[1][0]=fmaf(x0.y,w.x,acc[1][0]); acc[1][1]=fmaf(x0.y,w.y,acc[1][1]); acc[1][2]=fmaf(x0.y,w.z,acc[1][2]); acc[1][3]=fmaf(x0.y,w.w,acc[1][3]);
            acc[2][0]=fmaf(x0.z,w.x,acc[2][0]); acc[2][1]=fmaf(x0.z,w.y,acc[2][1]); acc[2][2]=fmaf(x0.z,w.z,acc[2][2]); acc[2][3]=fmaf(x0.z,w.w,acc[2][3]);
            acc[3][0]=fmaf(x0.w,w.x,acc[3][0]); acc[3][1]=fmaf(x0.w,w.y,acc[3][1]); acc[3][2]=fmaf(x0.w,w.z,acc[3][2]); acc[3][3]=fmaf(x0.w,w.w,acc[3][3]);
            acc[4][0]=fmaf(x1.x,w.x,acc[4][0]); acc[4][1]=fmaf(x1.x,w.y,acc[4][1]); acc[4][2]=fmaf(x1.x,w.z,acc[4][2]); acc[4][3]=fmaf(x1.x,w.w,acc[4][3]);
            acc[5][0]=fmaf(x1.y,w.x,acc[5][0]); acc[5][1]=fmaf(x1.y,w.y,acc[5][1]); acc[5][2]=fmaf(x1.y,w.z,acc[5][2]); acc[5][3]=fmaf(x1.y,w.w,acc[5][3]);
            acc[6][0]=fmaf(x1.z,w.x,acc[6][0]); acc[6][1]=fmaf(x1.z,w.y,acc[6][1]); acc[6][2]=fmaf(x1.z,w.z,acc[6][2]); acc[6][3]=fmaf(x1.z,w.w,acc[6][3]);
            acc[7][0]=fmaf(x1.w,w.x,acc[7][0]); acc[7][1]=fmaf(x1.w,w.y,acc[7][1]); acc[7][2]=fmaf(x1.w,w.z,acc[7][2]); acc[7][3]=fmaf(x1.w,w.w,acc[7][3]);
        }
        __syncthreads();
    }

    // epilogue: add bias, store to scratch
    float4 bias;
    float* dstBase;
    if (isRx) {
        bias = *(const float4*)(bb + n0 + tn*4);
        dstBase = g_xRx + (size_t)(n0 + tn*4);
    } else {
        bias = *(const float4*)(bd + (n0 - DD) + tn*4);
        dstBase = g_xWd + (size_t)((n0 - DD) + tn*4);
    }
    #pragma unroll
    for (int i = 0; i < 8; ++i) {
        const int row = m0 + tm*8 + i;
        float4 r;
        r.x = acc[i][0] + bias.x;
        r.y = acc[i][1] + bias.y;
        r.z = acc[i][2] + bias.z;
        r.w = acc[i][3] + bias.w;
        *(float4*)(dstBase + (size_t)row * DD) = r;
    }
}

// ---------------- barriers --------------------------------------------------
__device__ __forceinline__ void bar_group(int et, unsigned target) {
    __syncthreads();
    if (threadIdx.x == 0) {
        __threadfence();
        unsigned a = atomicAdd(&g_b1cnt[et*32], 1u);
        if (a == 3u) {
            atomicExch(&g_b1cnt[et*32], 0u);
            __threadfence();
            g_b1gen[et*32] = target;
        } else {
            while (g_b1gen[et*32] < target) __nanosleep(32);
            __threadfence();
        }
    }
    __syncthreads();
}

__device__ __forceinline__ void bar_global(int et, unsigned target) {
    __syncthreads();
    if (threadIdx.x == 0) {
        __threadfence();
        unsigned a = atomicAdd(&g_b1cnt[et*32], 1u);
        if (a == 3u) {
            atomicExch(&g_b1cnt[et*32], 0u);
            __threadfence();
            unsigned g = atomicAdd(&g_b2cnt, 1u);
            if (g == 31u) {
                atomicExch(&g_b2cnt, 0u);
                __threadfence();
                g_b2gen = target;
            }
        }
        while (g_b2gen < target) __nanosleep(32);
        __threadfence();
    }
    __syncthreads();
}

// ---------------- persistent scan kernel ------------------------------------
// grid = 128 blocks (<= 148 SMs -> all resident). block = (etile, ksplit):
//   etile et in [0,32): 32 e-values (both R_h and R_delta columns -> 64 cols)
//   ksplit ks in [0,4): K-chunk of 256
// R tiles cached in smem ONCE. Per step: stage h[t] chunk, partial GEMM,
// group barrier, fused reduce+nonlinearity+store, global barrier.
__global__ void __launch_bounds__(128) scan_kernel(
    const float* __restrict__ x,
    const float* __restrict__ Rh,
    const float* __restrict__ Rd,
    const float* __restrict__ b_gate,
    float* __restrict__ out,
    float* __restrict__ hout)
{
    extern __shared__ float smf[];
    float* As = smf;               // [256][32]  h chunk, [k][b]
    float* Bs = smf + 256*32;      // [256][64]  R chunk, [k][col]

    const int tid = threadIdx.x;
    const int et  = blockIdx.x >> 2;
    const int ks  = blockIdx.x & 3;
    const int e0  = et << 5;       // *32
    const int k0  = ks << 8;       // *256

    // load R tiles once (step-invariant)
    for (int i = tid; i < 64*64; i += 128) {
        const int col = i >> 6, kq = i & 63;
        const float* src = (col < 32) ? (Rh + (size_t)(e0 + col) * DD)
                                      : (Rd + (size_t)(e0 + col - 32) * DD);
        float4 v = *(const float4*)(src + k0 + kq*4);
        const int kk = kq * 4;
        Bs[(kk+0)*64 + col] = v.x;
        Bs[(kk+1)*64 + col] = v.y;
        Bs[(kk+2)*64 + col] = v.z;
        Bs[(kk+3)*64 + col] = v.w;
    }

    const int tbq = tid >> 4;      // 0..7  (b-quad)
    const int tcq = tid & 15;      // 0..15 (col-quad)
    const int hb  = tid & 31;
    const int hq0 = tid >> 5;      // 0..3
    const int wt  = ks * 128 + tid; // 0..511 thread id within etile group
    __syncthreads();

    for (int t = 0; t < TT; ++t) {
        // stage h[t] K-chunk: [32 b][256 k] -> As[k][b]
        const float* hrow = hout + (size_t)t*BD + (size_t)hb*DD + k0;
        #pragma unroll
        for (int j = 0; j < 16; ++j) {
            const int q = hq0 + (j << 2);
            float4 v = __ldcg((const float4*)(hrow + q*4));
            const int kk = q * 4;
            As[(kk+0)*32 + hb] = v.x;
            As[(kk+1)*32 + hb] = v.y;
            As[(kk+2)*32 + hb] = v.z;
            As[(kk+3)*32 + hb] = v.w;
        }
        __syncthreads();

        float acc[4][4];
        #pragma unroll
        for (int i = 0; i < 4; ++i)
            #pragma unroll
            for (int j = 0; j < 4; ++j) acc[i][j] = 0.f;

        #pragma unroll 8
        for (int k = 0; k < 256; ++k) {
            float4 a = *(const float4*)(As + (k << 5) + (tbq << 2));
            float4 c = *(const float4*)(Bs + (k << 6) + (tcq << 2));
            acc[0][0]=fmaf(a.x,c.x,acc[0][0]); acc[0][1]=fmaf(a.x,c.y,acc[0][1]); acc[0][2]=fmaf(a.x,c.z,acc[0][2]); acc[0][3]=fmaf(a.x,c.w,acc[0][3]);
            acc[1][0]=fmaf(a.y,c.x,acc[1][0]); acc[1][1]=fmaf(a.y,c.y,acc[1][1]); acc[1][2]=fmaf(a.y,c.z,acc[1][2]); acc[1][3]=fmaf(a.y,c.w,acc[1][3]);
            acc[2][0]=fmaf(a.z,c.x,acc[2][0]); acc[2][1]=fmaf(a.z,c.y,acc[2][1]); acc[2][2]=fmaf(a.z,c.z,acc[2][2]); acc[2][3]=fmaf(a.z,c.w,acc[2][3]);
            acc[3][0]=fmaf(a.w,c.x,acc[3][0]); acc[3][1]=fmaf(a.w,c.y,acc[3][1]); acc[3][2]=fmaf(a.w,c.z,acc[3][2]); acc[3][3]=fmaf(a.w,c.w,acc[3][3]);
        }

        // write split-K partials (L2-coherent)
        {
            const int col = tcq << 2;
            #pragma unroll
            for (int i = 0; i < 4; ++i) {
                const int b = (tbq << 2) + i;
                float4 w = make_float4(acc[i][0], acc[i][1], acc[i][2], acc[i][3]);
                if (col < 32)
                    __stcg((float4*)(g_pv + (((size_t)(ks*32 + b)) << 10) + e0 + col), w);
                else
                    __stcg((float4*)(g_pd + (((size_t)(ks*32 + b)) << 10) + e0 + col - 32), w);
            }
        }
        bar_group(et, (unsigned)(t + 1));

        // fused reduce + nonlinearity: the 4 group blocks own this etile's pairs
        #pragma unroll
        for (int r = 0; r < 2; ++r) {
            const int pi = wt + (r << 9);        // 0..1023 within etile
            const int b  = pi >> 5;
            const int e  = e0 + (pi & 31);
            const int p  = (b << 10) + e;
            const size_t idx = (size_t)t*BD + p;
            float sv = 0.f, sd = 0.f;
            #pragma unroll
            for (int s = 0; s < 4; ++s) {
                sv += __ldcg(g_pv + (size_t)s*BD + p);
                sd += __ldcg(g_pd + (size_t)s*BD + p);
            }
            const float v  = g_xRx[idx] + sv;
            const float dl = g_xWd[idx] + sd;
            const float delta = 1.f / (1.f + __expf(-dl));
            const float hp = __ldcg(hout + idx);
            const float hn = hp + delta * (tanhf(v) - hp);
            __stcg(hout + idx + BD, hn);
            const float z  = hn + x[idx] + b_gate[e];
            const float sg = 1.f / (1.f + __expf(-z));
            out[idx] = hn * z * sg;
        }
        bar_global(et, (unsigned)(t + 1));
    }
}

// ---------------- launch -----------------------------------------------------
extern "C" void kernel_launch(void* const* d_in, const int* in_sizes, int n_in,
                              void* d_out, int out_size) {
    const float* x  = (const float*)d_in[0];
    const float* h0 = (const float*)d_in[1];
    const float* Rh = (const float*)d_in[2];
    const float* Rx = (const float*)d_in[3];
    const float* Rd = (const float*)d_in[4];
    const float* Wd = (const float*)d_in[5];
    const float* bb = (const float*)d_in[6];
    const float* bd = (const float*)d_in[7];
    const float* bg = (const float*)d_in[8];

    float* out  = (float*)d_out;            // [T,B,D]
    float* hout = out + (size_t)TBD;        // [T+1,B,D]

    cudaFuncSetAttribute(scan_kernel, cudaFuncAttributeMaxDynamicSharedMemorySize, 98304);

    init_kernel<<<256, 128>>>(h0, hout);
    pre_gemm<<<8192, 256>>>(x, Rx, Wd, bb, bd);
    scan_kernel<<<128, 128, 98304>>>(x, Rh, Rd, bg, out, hout);
}

// round 6
// speedup vs baseline: 1.8345x; 1.8345x over previous
#include <cuda_runtime.h>
#include <cuda_bf16.h>
#include <cstdint>
#include <math.h>

#define TT 1024
#define DD 1024
#define BD 32768            // 32*1024
#define TBD (TT*BD)

// ---------------- device scratch --------------------------------------------
__device__ float g_xRx[TBD];                 // x @ R_x^T + b
__device__ float g_xWd[TBD];                 // x @ W_delta^T + b_delta
__device__ __nv_bfloat16 g_xhi[TBD];         // x split hi
__device__ __nv_bfloat16 g_xlo[TBD];         // x split lo
__device__ __nv_bfloat16 g_wxh[2048*1024];   // [Rx; Wd] split hi, row-major [n][k]
__device__ __nv_bfloat16 g_wxl[2048*1024];   // [Rx; Wd] split lo
__device__ unsigned g_b1cnt[16*32];
__device__ unsigned g_b2cnt;
__device__ volatile unsigned g_b2gen;

// ---------------- helpers ---------------------------------------------------
__device__ __forceinline__ uint32_t smem_u32(const void* p) {
    uint32_t a;
    asm("{ .reg .u64 t; cvta.to.shared.u64 t, %1; cvt.u32.u64 %0, t; }" : "=r"(a) : "l"(p));
    return a;
}

__device__ __forceinline__ void split2(float a, float b, uint32_t& hi, uint32_t& lo) {
    __nv_bfloat16 ha = __float2bfloat16(a);
    __nv_bfloat16 hb = __float2bfloat16(b);
    __nv_bfloat16 la = __float2bfloat16(a - __bfloat162float(ha));
    __nv_bfloat16 lb = __float2bfloat16(b - __bfloat162float(hb));
    __nv_bfloat162 H = __halves2bfloat162(ha, hb);
    __nv_bfloat162 L = __halves2bfloat162(la, lb);
    hi = *reinterpret_cast<uint32_t*>(&H);
    lo = *reinterpret_cast<uint32_t*>(&L);
}

__device__ __forceinline__ void mma_bf16(float* c, const uint32_t* a, uint32_t b0, uint32_t b1) {
    asm volatile("mma.sync.aligned.m16n8k16.row.col.f32.bf16.bf16.f32 "
        "{%0,%1,%2,%3}, {%4,%5,%6,%7}, {%8,%9}, {%0,%1,%2,%3};"
        : "+f"(c[0]), "+f"(c[1]), "+f"(c[2]), "+f"(c[3])
        : "r"(a[0]), "r"(a[1]), "r"(a[2]), "r"(a[3]), "r"(b0), "r"(b1));
}

__device__ __forceinline__ void ldmat4(uint32_t* r, uint32_t addr) {
    asm volatile("ldmatrix.sync.aligned.m8n8.x4.shared.b16 {%0,%1,%2,%3}, [%4];"
        : "=r"(r[0]), "=r"(r[1]), "=r"(r[2]), "=r"(r[3]) : "r"(addr));
}

#define CP_ASYNC16(dst, src) \
    asm volatile("cp.async.cg.shared.global [%0], [%1], 16;" :: "r"(dst), "l"(src) : "memory")
#define CP_COMMIT() asm volatile("cp.async.commit_group;" ::: "memory")
#define CP_WAIT(n)  asm volatile("cp.async.wait_group %0;" :: "n"(n) : "memory")

// ---------------- init ------------------------------------------------------
__global__ void init_kernel(const float* __restrict__ h0, float* __restrict__ hout) {
    int i = blockIdx.x * blockDim.x + threadIdx.x;
    if (i < BD) hout[i] = h0[i];
    if (i < 16) g_b1cnt[i*32] = 0u;
    if (i == 0) { g_b2cnt = 0u; g_b2gen = 0u; }
}

// ---------------- split kernels ---------------------------------------------
__global__ void split_x(const float* __restrict__ x) {
    size_t i = (size_t)blockIdx.x * 512 + threadIdx.x;
    const float4* xv = (const float4*)x;
    #pragma unroll
    for (int j = 0; j < 2; ++j) {
        size_t idx = i + (size_t)j * 256;
        float4 v = xv[idx];
        uint32_t h0_, l0_, h1_, l1_;
        split2(v.x, v.y, h0_, l0_);
        split2(v.z, v.w, h1_, l1_);
        ((uint2*)g_xhi)[idx] = make_uint2(h0_, h1_);
        ((uint2*)g_xlo)[idx] = make_uint2(l0_, l1_);
    }
}

__global__ void split_w(const float* __restrict__ Rx, const float* __restrict__ Wd) {
    int row = blockIdx.x;
    int k = threadIdx.x * 4;
    const float* src = (row < 1024) ? (Rx + (size_t)row * 1024) : (Wd + (size_t)(row - 1024) * 1024);
    float4 v = *(const float4*)(src + k);
    uint32_t h0_, l0_, h1_, l1_;
    split2(v.x, v.y, h0_, l0_);
    split2(v.z, v.w, h1_, l1_);
    ((uint2*)g_wxh)[(size_t)row * 256 + threadIdx.x] = make_uint2(h0_, h1_);
    ((uint2*)g_wxl)[(size_t)row * 256 + threadIdx.x] = make_uint2(l0_, l1_);
}

// ---------------- precompute GEMM via bf16 mma.sync -------------------------
// C[32768 x 2048] = X @ [Rx; Wd]^T, 3-pass split-bf16, block tile 128x64, BK=32
#define PG_SXH 0
#define PG_SXL 10240
#define PG_SWH 20480
#define PG_SWL 25600
#define PG_STG 30720

__global__ void __launch_bounds__(256) pre_gemm_mma(
    const float* __restrict__ bb, const float* __restrict__ bd)
{
    extern __shared__ char sm[];
    const uint32_t smb = smem_u32(sm);
    const int tid = threadIdx.x;
    const int lane = tid & 31;
    const int wid = tid >> 5;
    const int wm = wid >> 1;          // 0..3
    const int wn = wid & 1;           // 0..1
    const int mt = blockIdx.x >> 5;
    const int nt = blockIdx.x & 31;
    const int m0 = mt << 7;
    const int n0 = nt << 6;

    const int xrow0 = tid >> 2, xq = tid & 3;     // X copy map (j adds 64 rows)
    const int wrow  = tid >> 2, wq = tid & 3;     // W copy map

    float acc[8][4];
    #pragma unroll
    for (int i = 0; i < 8; ++i)
        #pragma unroll
        for (int j = 0; j < 4; ++j) acc[i][j] = 0.f;

    // per-lane smem offsets
    const uint32_t a_base = (uint32_t)(((wm*32 + ((lane>>3)&1)*8 + (lane&7)) * 40
                                      + ((lane>>4)&1)*8) * 2);
    const uint32_t b_base = (uint32_t)(((wn*32 + (lane>>2)) * 40 + (lane&3)*2) * 2);

    // prologue copy tile 0
    {
        const int k0 = 0;
        #pragma unroll
        for (int j = 0; j < 2; ++j) {
            const int row = xrow0 + j*64;
            const size_t g = (size_t)(m0 + row) * 1024 + k0 + xq*8;
            CP_ASYNC16(smb + PG_SXH + row*80 + xq*16, g_xhi + g);
            CP_ASYNC16(smb + PG_SXL + row*80 + xq*16, g_xlo + g);
        }
        const size_t gw = (size_t)(n0 + wrow) * 1024 + k0 + wq*8;
        CP_ASYNC16(smb + PG_SWH + wrow*80 + wq*16, g_wxh + gw);
        CP_ASYNC16(smb + PG_SWL + wrow*80 + wq*16, g_wxl + gw);
        CP_COMMIT();
    }

    for (int kt = 0; kt < 32; ++kt) {
        if (kt < 31) {
            const int k0 = (kt + 1) * 32;
            const uint32_t sb = smb + ((kt + 1) & 1) * PG_STG;
            #pragma unroll
            for (int j = 0; j < 2; ++j) {
                const int row = xrow0 + j*64;
                const size_t g = (size_t)(m0 + row) * 1024 + k0 + xq*8;
                CP_ASYNC16(sb + PG_SXH + row*80 + xq*16, g_xhi + g);
                CP_ASYNC16(sb + PG_SXL + row*80 + xq*16, g_xlo + g);
            }
            const size_t gw = (size_t)(n0 + wrow) * 1024 + k0 + wq*8;
            CP_ASYNC16(sb + PG_SWH + wrow*80 + wq*16, g_wxh + gw);
            CP_ASYNC16(sb + PG_SWL + wrow*80 + wq*16, g_wxl + gw);
            CP_COMMIT();
            CP_WAIT(1);
        } else {
            CP_WAIT(0);
        }
        __syncthreads();

        const uint32_t sb = smb + (kt & 1) * PG_STG;
        const char*   sp = sm  + (kt & 1) * PG_STG;
        #pragma unroll
        for (int ks = 0; ks < 2; ++ks) {
            const uint32_t kb = ks * 32;
            uint32_t Ah[2][4], Al[2][4];
            #pragma unroll
            for (int mi = 0; mi < 2; ++mi) {
                ldmat4(Ah[mi], sb + PG_SXH + a_base + mi*1280 + kb);
                ldmat4(Al[mi], sb + PG_SXL + a_base + mi*1280 + kb);
            }
            #pragma unroll
            for (int nt2 = 0; nt2 < 4; ++nt2) {
                const uint32_t bo = b_base + nt2*640 + kb;
                uint32_t bh0 = *(const uint32_t*)(sp + PG_SWH + bo);
                uint32_t bh1 = *(const uint32_t*)(sp + PG_SWH + bo + 16);
                uint32_t bl0 = *(const uint32_t*)(sp + PG_SWL + bo);
                uint32_t bl1 = *(const uint32_t*)(sp + PG_SWL + bo + 16);
                #pragma unroll
                for (int mi = 0; mi < 2; ++mi) {
                    mma_bf16(acc[mi*4+nt2], Ah[mi], bh0, bh1);
                    mma_bf16(acc[mi*4+nt2], Ah[mi], bl0, bl1);
                    mma_bf16(acc[mi*4+nt2], Al[mi], bh0, bh1);
                }
            }
        }
        __syncthreads();
    }

    // epilogue: add bias, store fp32
    const bool isRx = (n0 < 1024);
    float* dst = isRx ? g_xRx : g_xWd;
    const float* bias = isRx ? bb : bd;
    const int nrel0 = isRx ? n0 : (n0 - 1024);
    #pragma unroll
    for (int mi = 0; mi < 2; ++mi) {
        #pragma unroll
        for (int nt2 = 0; nt2 < 4; ++nt2) {
            const int col = nrel0 + wn*32 + nt2*8 + (lane&3)*2;
            const float2 bv = *(const float2*)(bias + col);
            const int r0 = m0 + wm*32 + mi*16 + (lane>>2);
            const float* c = acc[mi*4+nt2];
            float2 o0 = make_float2(c[0] + bv.x, c[1] + bv.y);
            float2 o1 = make_float2(c[2] + bv.x, c[3] + bv.y);
            *(float2*)(dst + (size_t)r0 * 1024 + col) = o0;
            *(float2*)(dst + (size_t)(r0+8) * 1024 + col) = o1;
        }
    }
}

// ---------------- global barrier (64 blocks, 16 groups of 4) ----------------
__device__ __forceinline__ void bar_global(int grp, unsigned target) {
    __syncthreads();
    if (threadIdx.x == 0) {
        __threadfence();
        unsigned a = atomicAdd(&g_b1cnt[grp*32], 1u);
        if (a == 3u) {
            atomicExch(&g_b1cnt[grp*32], 0u);
            unsigned g = atomicAdd(&g_b2cnt, 1u);
            if (g == 15u) { atomicExch(&g_b2cnt, 0u); __threadfence(); g_b2gen = target; }
        }
        while (g_b2gen < target) __nanosleep(20);
        __threadfence();
    }
    __syncthreads();
}

// ---------------- persistent scan kernel (bf16 mma.sync) --------------------
// 64 blocks, each owns 16 e-outputs, full K=1024.
// C[32 batch x 32 cols] where cols 0-15 = v (Rh), 16-31 = delta (Rd).
#define SC_WH 0                   // W hi: [32][1032] bf16 = 66048 B
#define SC_WL 66048
#define SC_HB 132096              // 2 bufs x (hi 16896 + lo 16896) = 67584
#define SC_HBUF 33792
#define SC_HLO 16896
#define SC_CS 199680              // Cs[32][36] f32 = 4608
#define SC_TOTAL 204288

__global__ void __launch_bounds__(256, 1) scan_mma(
    const float* __restrict__ x,
    const float* __restrict__ Rh,
    const float* __restrict__ Rd,
    const float* __restrict__ b_gate,
    float* __restrict__ out,
    float* __restrict__ hout)
{
    extern __shared__ char sm[];
    const uint32_t smb = smem_u32(sm);
    const int tid = threadIdx.x;
    const int lane = tid & 31;
    const int wid = tid >> 5;
    const int wmi = wid >> 2;     // 0..1 (batch m-tile)
    const int wni = wid & 3;      // 0..3 (col n-tile)
    const int blk = blockIdx.x;
    const int e0 = blk << 4;      // *16

    // ---- load W (32 cols x 1024 k) split hi/lo, padded stride 1032 ----
    {
        const int r = tid >> 3;            // 0..31 col index
        const int seg = tid & 7;
        const float* src = (r < 16) ? (Rh + (size_t)(e0 + r) * DD)
                                    : (Rd + (size_t)(e0 + r - 16) * DD);
        char* wh = sm + SC_WH + r * 2064;
        char* wl = sm + SC_WL + r * 2064;
        #pragma unroll 4
        for (int i = 0; i < 32; ++i) {
            const int k = seg * 128 + i * 4;
            float4 v = *(const float4*)(src + k);
            uint32_t h0_, l0_, h1_, l1_;
            split2(v.x, v.y, h0_, l0_);
            split2(v.z, v.w, h1_, l1_);
            *(uint2*)(wh + k * 2) = make_uint2(h0_, h1_);
            *(uint2*)(wl + k * 2) = make_uint2(l0_, l1_);
        }
    }

    // pointwise mapping: thread owns 2 consecutive e for one batch row
    const int pb = tid >> 3;               // 0..31 batch
    const int pel = (tid & 7) * 2;         // 0..14 even
    const int eg = e0 + pel;
    const size_t pgo = (size_t)pb * DD + eg;
    const float2 bg2 = *(const float2*)(b_gate + eg);
    float2 hp = *(const float2*)(hout + pgo);     // h0

    // mma lane offsets
    const uint32_t a_off = (uint32_t)((wmi*16 + ((lane>>3)&1)*8 + (lane&7)) * 528
                                    + ((lane>>4)&1)*16);
    const uint32_t b_off = (uint32_t)((wni*8 + (lane>>2)) * 2064 + (lane&3)*4);
    float* Cs = (float*)(sm + SC_CS);

    __syncthreads();

    for (int t = 0; t < TT; ++t) {
        const size_t tg = (size_t)t * BD;

        // prefetch pointwise operands (used ~4000 cyc later)
        const float2 xr = *(const float2*)(g_xRx + tg + pgo);
        const float2 xw = *(const float2*)(g_xWd + tg + pgo);
        const float2 xx = *(const float2*)(x + tg + pgo);

        // ---- stage chunk 0 into buf0 ----
        {
            const float* hsrc = hout + tg;
            char* bh = sm + SC_HB;
            char* bl = bh + SC_HLO;
            #pragma unroll
            for (int i = 0; i < 8; ++i) {
                const int idx = tid + i * 256;
                const int b = idx >> 6, kq = idx & 63;
                float4 v = __ldcg((const float4*)(hsrc + (size_t)b * DD + kq * 4));
                uint32_t h0_, l0_, h1_, l1_;
                split2(v.x, v.y, h0_, l0_);
                split2(v.z, v.w, h1_, l1_);
                *(uint2*)(bh + b*528 + kq*8) = make_uint2(h0_, h1_);
                *(uint2*)(bl + b*528 + kq*8) = make_uint2(l0_, l1_);
            }
        }
        __syncthreads();

        float accE[4] = {0.f,0.f,0.f,0.f};
        float accO[4] = {0.f,0.f,0.f,0.f};

        for (int c = 0; c < 4; ++c) {
            // prefetch next chunk h data
            float4 pf[8];
            if (c < 3) {
                const float* hsrc = hout + tg + (c + 1) * 256;
                #pragma unroll
                for (int i = 0; i < 8; ++i) {
                    const int idx = tid + i * 256;
                    const int b = idx >> 6, kq = idx & 63;
                    pf[i] = __ldcg((const float4*)(hsrc + (size_t)b * DD + kq * 4));
                }
            }

            const uint32_t hbase = smb + SC_HB + (uint32_t)((c & 1) * SC_HBUF);
            const uint32_t wc = (uint32_t)(c * 512);

            // first half: ks 0..7
            #pragma unroll
            for (int ks = 0; ks < 8; ++ks) {
                const uint32_t akb = ks * 32;
                const uint32_t wkb = wc + akb;
                uint32_t Ah[4], Al[4];
                ldmat4(Ah, hbase + a_off + akb);
                ldmat4(Al, hbase + SC_HLO + a_off + akb);
                uint32_t bh0 = *(const uint32_t*)(sm + SC_WH + b_off + wkb);
                uint32_t bh1 = *(const uint32_t*)(sm + SC_WH + b_off + wkb + 16);
                uint32_t bl0 = *(const uint32_t*)(sm + SC_WL + b_off + wkb);
                uint32_t bl1 = *(const uint32_t*)(sm + SC_WL + b_off + wkb + 16);
                float* acc = (ks & 1) ? accO : accE;
                mma_bf16(acc, Ah, bh0, bh1);
                mma_bf16(acc, Ah, bl0, bl1);
                mma_bf16(acc, Al, bh0, bh1);
            }
            // convert+store first half of next chunk (overlaps tensor pipe)
            if (c < 3) {
                char* bh = sm + SC_HB + ((c + 1) & 1) * SC_HBUF;
                char* bl = bh + SC_HLO;
                #pragma unroll
                for (int i = 0; i < 4; ++i) {
                    const int idx = tid + i * 256;
                    const int b = idx >> 6, kq = idx & 63;
                    uint32_t h0_, l0_, h1_, l1_;
                    split2(pf[i].x, pf[i].y, h0_, l0_);
                    split2(pf[i].z, pf[i].w, h1_, l1_);
                    *(uint2*)(bh + b*528 + kq*8) = make_uint2(h0_, h1_);
                    *(uint2*)(bl + b*528 + kq*8) = make_uint2(l0_, l1_);
                }
            }
            // second half: ks 8..15
            #pragma unroll
            for (int ks = 8; ks < 16; ++ks) {
                const uint32_t akb = ks * 32;
                const uint32_t wkb = wc + akb;
                uint32_t Ah[4], Al[4];
                ldmat4(Ah, hbase + a_off + akb);
                ldmat4(Al, hbase + SC_HLO + a_off + akb);
                uint32_t bh0 = *(const uint32_t*)(sm + SC_WH + b_off + wkb);
                uint32_t bh1 = *(const uint32_t*)(sm + SC_WH + b_off + wkb + 16);
                uint32_t bl0 = *(const uint32_t*)(sm + SC_WL + b_off + wkb);
                uint32_t bl1 = *(const uint32_t*)(sm + SC_WL + b_off + wkb + 16);
                float* acc = (ks & 1) ? accO : accE;
                mma_bf16(acc, Ah, bh0, bh1);
                mma_bf16(acc, Ah, bl0, bl1);
                mma_bf16(acc, Al, bh0, bh1);
            }
            if (c < 3) {
                char* bh = sm + SC_HB + ((c + 1) & 1) * SC_HBUF;
                char* bl = bh + SC_HLO;
                #pragma unroll
                for (int i = 4; i < 8; ++i) {
                    const int idx = tid + i * 256;
                    const int b = idx >> 6, kq = idx & 63;
                    uint32_t h0_, l0_, h1_, l1_;
                    split2(pf[i].x, pf[i].y, h0_, l0_);
                    split2(pf[i].z, pf[i].w, h1_, l1_);
                    *(uint2*)(bh + b*528 + kq*8) = make_uint2(h0_, h1_);
                    *(uint2*)(bl + b*528 + kq*8) = make_uint2(l0_, l1_);
                }
            }
            __syncthreads();
        }

        // ---- epilogue: park C in smem ----
        {
            const int r0 = wmi*16 + (lane >> 2);
            const int col = wni*8 + (lane & 3)*2;
            float2 v0 = make_float2(accE[0] + accO[0], accE[1] + accO[1]);
            float2 v1 = make_float2(accE[2] + accO[2], accE[3] + accO[3]);
            *(float2*)(Cs + r0*36 + col) = v0;
            *(float2*)(Cs + (r0+8)*36 + col) = v1;
        }
        __syncthreads();

        // ---- pointwise ----
        {
            const float v0 = xr.x + Cs[pb*36 + pel];
            const float v1 = xr.y + Cs[pb*36 + pel + 1];
            const float dl0 = xw.x + Cs[pb*36 + 16 + pel];
            const float dl1 = xw.y + Cs[pb*36 + 16 + pel + 1];
            const float d0 = 1.f / (1.f + __expf(-dl0));
            const float d1 = 1.f / (1.f + __expf(-dl1));
            const float hn0 = hp.x + d0 * (tanhf(v0) - hp.x);
            const float hn1 = hp.y + d1 * (tanhf(v1) - hp.y);
            const float z0 = hn0 + xx.x + bg2.x;
            const float z1 = hn1 + xx.y + bg2.y;
            float2 ho = make_float2(hn0, hn1);
            float2 oo = make_float2(hn0 * z0 / (1.f + __expf(-z0)),
                                    hn1 * z1 / (1.f + __expf(-z1)));
            *(float2*)(hout + tg + BD + pgo) = ho;
            *(float2*)(out + tg + pgo) = oo;
            hp = ho;
        }

        bar_global(blk >> 2, (unsigned)(t + 1));
    }
}

// ---------------- launch ----------------------------------------------------
extern "C" void kernel_launch(void* const* d_in, const int* in_sizes, int n_in,
                              void* d_out, int out_size) {
    const float* x  = (const float*)d_in[0];
    const float* h0 = (const float*)d_in[1];
    const float* Rh = (const float*)d_in[2];
    const float* Rx = (const float*)d_in[3];
    const float* Rd = (const float*)d_in[4];
    const float* Wd = (const float*)d_in[5];
    const float* bb = (const float*)d_in[6];
    const float* bd = (const float*)d_in[7];
    const float* bg = (const float*)d_in[8];

    float* out  = (float*)d_out;           // [T,B,D]
    float* hout = out + (size_t)TBD;       // [T+1,B,D]

    cudaFuncSetAttribute(pre_gemm_mma, cudaFuncAttributeMaxDynamicSharedMemorySize, 2*PG_STG);
    cudaFuncSetAttribute(scan_mma, cudaFuncAttributeMaxDynamicSharedMemorySize, SC_TOTAL);

    init_kernel<<<256, 128>>>(h0, hout);
    split_x<<<16384, 256>>>(x);
    split_w<<<2048, 256>>>(Rx, Wd);
    pre_gemm_mma<<<8192, 256, 2*PG_STG>>>(bb, bd);
    scan_mma<<<64, 256, SC_TOTAL>>>(x, Rh, Rd, bg, out, hout);
}